// round 15
// baseline (speedup 1.0000x reference)
#include <cuda_runtime.h>
#include <math.h>

#define K_CB 196560
#define EMB 24
#define TT 10
#define NBARS_TOTAL 22

// ---------------- device scratch (static allocation only) ----------------
__device__ float g_res[12288];                   // residual [2][24][16][16]
__device__ float g_rdown[512 * EMB];             // downsampled tokens [N][24]
__device__ float g_zq[512 * EMB];                // quantized tokens (post-STE)
__device__ unsigned long long g_bestbuf[2][512]; // double-buffered (sim,~idx)
__device__ float g_wd[10][16][16];               // down weights
__device__ float g_wu[10][16][16];               // up weights
__device__ int g_barcnt;                         // grid barrier arrivals
__device__ int g_bargen;                         // grid barrier generation
// vector-planar codebook: plane k holds 16B-chunk k of every row,
// so a warp reading consecutive rows is fully coalesced (4 wf/LDG).
__device__ ulonglong2 g_cbT[6 * K_CB];           // 18.87 MB

__constant__ int c_hs[10] = {1, 2, 3, 4, 5, 6, 8, 10, 13, 16};

// ---------------- helpers ----------------
__device__ __forceinline__ unsigned int forder(float f) {
    unsigned int u = __float_as_uint(f);
    return (u & 0x80000000u) ? ~u : (u | 0x80000000u);
}
__device__ __forceinline__ unsigned long long ffma2(unsigned long long a,
                                                    unsigned long long b,
                                                    unsigned long long c) {
    unsigned long long d;
    asm("fma.rn.f32x2 %0, %1, %2, %3;" : "=l"(d) : "l"(a), "l"(b), "l"(c));
    return d;
}
__device__ __forceinline__ float2 unpackf2(unsigned long long v) {
    float lo, hi;
    asm("mov.b64 {%0, %1}, %2;" : "=f"(lo), "=f"(hi) : "l"(v));
    return make_float2(lo, hi);
}

// jax.image.resize compute_weight_mat (triangle kernel, antialias, tr=0)
__device__ void compute_col(int in_size, int out_size, int o, float* wcol) {
    float inv_scale = (float)((double)in_size / (double)out_size);
    float kscale = fmaxf(inv_scale, 1.0f);
    float sample_f = ((float)o + 0.5f) * inv_scale - 0.5f;
    float total = 0.0f;
    for (int i = 0; i < in_size; ++i) {
        float x = fabsf(sample_f - (float)i) / kscale;
        float w = fmaxf(0.0f, 1.0f - x);
        wcol[i] = w;
        total += w;
    }
    bool ok = fabsf(total) > 1000.0f * 1.1920928955078125e-7f;
    float denom = (total != 0.0f) ? total : 1.0f;
    bool inr = (sample_f >= -0.5f) && (sample_f <= (float)in_size - 0.5f);
    for (int i = 0; i < in_size; ++i) {
        float w = ok ? (wcol[i] / denom) : 0.0f;
        wcol[i] = inr ? w : 0.0f;
    }
}

// generation-counter grid barrier; gen is a per-thread local tracker
__device__ __forceinline__ void grid_barrier(int& gen) {
    __syncthreads();
    if (threadIdx.x == 0) {
        __threadfence();
        if (atomicAdd(&g_barcnt, 1) == (int)gridDim.x - 1) {
            atomicExch(&g_barcnt, 0);
            __threadfence();
            atomicAdd(&g_bargen, 1);
        } else {
            while (atomicAdd(&g_bargen, 0) < gen + 1) __nanosleep(64);
        }
        __threadfence();
    }
    gen++;
    __syncthreads();
}

// exact per-(row,token) dot order used since R5 (do not reorder)
#define ROW_DOT6(acc, q0, q1, q2, q3, q4, q5)                \
    do {                                                     \
        acc = ffma2(q0.x, z0.x, 0ull);                       \
        acc = ffma2(q0.y, z0.y, acc);                        \
        acc = ffma2(q1.x, z1.x, acc);                        \
        acc = ffma2(q1.y, z1.y, acc);                        \
        acc = ffma2(q2.x, z2.x, acc);                        \
        acc = ffma2(q2.y, z2.y, acc);                        \
        acc = ffma2(q3.x, z3.x, acc);                        \
        acc = ffma2(q3.y, z3.y, acc);                        \
        acc = ffma2(q4.x, z4.x, acc);                        \
        acc = ffma2(q4.y, z4.y, acc);                        \
        acc = ffma2(q5.x, z5.x, acc);                        \
        acc = ffma2(q5.y, z5.y, acc);                        \
    } while (0)

// ---------------- the whole algorithm in one persistent kernel -----------
__global__ void __launch_bounds__(256, 3)
fused_kernel(const float* __restrict__ z, const float* __restrict__ cb,
             float* __restrict__ out) {
    __shared__ __align__(16) float s_tok[TT][24];
    __shared__ unsigned long long s_wred[8][TT];
    __shared__ float s_a[16][16];
    __shared__ float s_b[16][16];
    __shared__ float s_c[16][16];
    __shared__ int s_base;

    int tid = threadIdx.x;
    int blk = blockIdx.x;
    int NB = gridDim.x;

    // per-run barrier base (replay-safe: g_bargen advances exactly
    // NBARS_TOTAL per run; all entry reads happen before first release)
    if (tid == 0) {
        int g = atomicAdd(&g_bargen, 0);
        s_base = (g / NBARS_TOTAL) * NBARS_TOTAL;
    }
    __syncthreads();
    int gen = s_base;

    // ---- phase 0: transpose codebook + residual copy + weights ----------
    {
        // coalesced read, planar scatter write (one pass, ~19MB)
        const ulonglong2* cbu = (const ulonglong2*)cb;
        for (int i = blk * 256 + tid; i < K_CB * 6; i += NB * 256) {
            int r = i / 6, k = i % 6;
            g_cbT[k * K_CB + r] = __ldg(cbu + i);
        }
    }
    if (blk < 48) {
        g_res[blk * 256 + tid] = z[blk * 256 + tid];
        out[blk * 256 + tid] = 0.0f;
        if (blk == 0) {
            for (int i = tid; i < 1024; i += 256)
                ((unsigned long long*)g_bestbuf)[i] = 0ull;
        }
    } else if (blk < 48 + 196) {
        if (tid == 0) {
            const int hs9[9] = {1, 2, 3, 4, 5, 6, 8, 10, 13};
            int task = blk - 48;
            float wcol[16];
            if (task < 52) {
                int rem = task, s = 0;
                while (rem >= hs9[s]) { rem -= hs9[s]; s++; }
                compute_col(16, hs9[s], rem, wcol);
                for (int i = 0; i < 16; i++) g_wd[s][i][rem] = wcol[i];
            } else {
                int r = task - 52;
                int s = r / 16, o = r % 16;
                compute_col(hs9[s], 16, o, wcol);
                for (int i = 0; i < 16; i++)
                    g_wu[s][i][o] = (i < hs9[s]) ? wcol[i] : 0.0f;
            }
        }
    }
    grid_barrier(gen);

    // ---- scale-0 downsample (h=1), blocks 0..47, one (b,d) plane each ---
    if (blk < 48) {
        int b = blk / 24, d = blk % 24;
        s_a[tid >> 4][tid & 15] = g_res[blk * 256 + tid];
        __syncthreads();
        if (tid < 16) {
            float acc = 0.0f;
            for (int Y = 0; Y < 16; Y++) acc += g_wd[0][Y][0] * s_a[Y][tid];
            s_b[0][tid] = acc;
        }
        __syncthreads();
        if (tid == 0) {
            float acc = 0.0f;
            for (int X = 0; X < 16; X++) acc += g_wd[0][X][0] * s_b[0][X];
            g_rdown[b * EMB + d] = acc;
        }
    }
    grid_barrier(gen);

    // ---- 10 scales ----
    int off = 12288;
    for (int s = 0; s < 10; s++) {
        int h = c_hs[s];
        int N = 2 * h * h;
        int tiles = (N + TT - 1) / TT;
        int nsl = NB / tiles;
        int tile = blk % tiles;
        int slice = blk / tiles;
        unsigned long long* best = g_bestbuf[s & 1];

        // ================= scan (coalesced planar codebook) ==============
        if (slice < nsl) {
            int token0 = tile * TT;
            for (int i = tid; i < TT * 24; i += 256) {
                int t = i / 24, d = i % 24;
                int tk = token0 + t;
                s_tok[t][d] = (tk < N) ? __ldcg(&g_rdown[tk * EMB + d]) : 0.0f;
            }
            __syncthreads();

            float bestv[TT];
            int besti[TT];
#pragma unroll
            for (int t = 0; t < TT; t++) { bestv[t] = -3.4e38f; besti[t] = 0; }

            int rpb = (K_CB + nsl - 1) / nsl;
            int rbeg = slice * rpb;
            int rend = min(K_CB, rbeg + rpb);

            int base = rbeg;
            for (; base + 512 <= rend; base += 512) {
                int rA = base + tid, rB = rA + 256;
                ulonglong2 a0 = __ldg(&g_cbT[0 * K_CB + rA]);
                ulonglong2 a1 = __ldg(&g_cbT[1 * K_CB + rA]);
                ulonglong2 a2 = __ldg(&g_cbT[2 * K_CB + rA]);
                ulonglong2 a3 = __ldg(&g_cbT[3 * K_CB + rA]);
                ulonglong2 a4 = __ldg(&g_cbT[4 * K_CB + rA]);
                ulonglong2 a5 = __ldg(&g_cbT[5 * K_CB + rA]);
                ulonglong2 b0 = __ldg(&g_cbT[0 * K_CB + rB]);
                ulonglong2 b1 = __ldg(&g_cbT[1 * K_CB + rB]);
                ulonglong2 b2 = __ldg(&g_cbT[2 * K_CB + rB]);
                ulonglong2 b3 = __ldg(&g_cbT[3 * K_CB + rB]);
                ulonglong2 b4 = __ldg(&g_cbT[4 * K_CB + rB]);
                ulonglong2 b5 = __ldg(&g_cbT[5 * K_CB + rB]);
#pragma unroll
                for (int t = 0; t < TT; t++) {
                    const ulonglong2* tz = (const ulonglong2*)s_tok[t];
                    ulonglong2 z0 = tz[0], z1 = tz[1], z2 = tz[2];
                    ulonglong2 z3 = tz[3], z4 = tz[4], z5 = tz[5];
                    unsigned long long accA, accB;
                    ROW_DOT6(accA, a0, a1, a2, a3, a4, a5);
                    ROW_DOT6(accB, b0, b1, b2, b3, b4, b5);
                    float2 fa = unpackf2(accA);
                    float2 fb = unpackf2(accB);
                    float simA = fa.x + fa.y;
                    float simB = fb.x + fb.y;
                    if (simA > bestv[t]) { bestv[t] = simA; besti[t] = rA; }
                    if (simB > bestv[t]) { bestv[t] = simB; besti[t] = rB; }
                }
            }
            // tail: single rows
            for (int r = base + tid; r < rend; r += 256) {
                ulonglong2 q0 = __ldg(&g_cbT[0 * K_CB + r]);
                ulonglong2 q1 = __ldg(&g_cbT[1 * K_CB + r]);
                ulonglong2 q2 = __ldg(&g_cbT[2 * K_CB + r]);
                ulonglong2 q3 = __ldg(&g_cbT[3 * K_CB + r]);
                ulonglong2 q4 = __ldg(&g_cbT[4 * K_CB + r]);
                ulonglong2 q5 = __ldg(&g_cbT[5 * K_CB + r]);
#pragma unroll
                for (int t = 0; t < TT; t++) {
                    const ulonglong2* tz = (const ulonglong2*)s_tok[t];
                    ulonglong2 z0 = tz[0], z1 = tz[1], z2 = tz[2];
                    ulonglong2 z3 = tz[3], z4 = tz[4], z5 = tz[5];
                    unsigned long long acc;
                    ROW_DOT6(acc, q0, q1, q2, q3, q4, q5);
                    float2 s2 = unpackf2(acc);
                    float sim = s2.x + s2.y;
                    if (sim > bestv[t]) { bestv[t] = sim; besti[t] = r; }
                }
            }

            unsigned long long pk[TT];
#pragma unroll
            for (int t = 0; t < TT; t++)
                pk[t] = ((unsigned long long)forder(bestv[t]) << 32) |
                        (unsigned long long)((unsigned)~besti[t]);
#pragma unroll
            for (int t = 0; t < TT; t++) {
#pragma unroll
                for (int o2 = 16; o2; o2 >>= 1) {
                    unsigned long long o = __shfl_down_sync(0xFFFFFFFFu, pk[t], o2);
                    if (o > pk[t]) pk[t] = o;
                }
            }
            int warp = tid >> 5, lane = tid & 31;
            if (lane == 0) {
#pragma unroll
                for (int t = 0; t < TT; t++) s_wred[warp][t] = pk[t];
            }
            __syncthreads();
            if (tid < TT) {
                unsigned long long m = s_wred[0][tid];
#pragma unroll
                for (int w = 1; w < 8; w++) {
                    unsigned long long v = s_wred[w][tid];
                    if (v > m) m = v;
                }
                if (token0 + tid < N) atomicMax(&best[token0 + tid], m);
            }
        }
        grid_barrier(gen);

        // ============ finalize (redundant per block) + updown ============
        if (blk < 48) {
            // finalize all N tokens (identical values from every block)
            for (int n = tid; n < N; n += 256) {
                unsigned long long pkv = __ldcg(&best[n]);
                unsigned row = ~((unsigned)(pkv & 0xFFFFFFFFull));
                out[off + n] = (float)row;
                const float* c = cb + (size_t)row * EMB;
                float ss = 0.0f;
                for (int d = 0; d < EMB; d++) { float v = c[d]; ss += v * v; }
                float nrm = sqrtf(ss);
                for (int d = 0; d < EMB; d++) {
                    float q = c[d] / nrm;
                    float zf = __ldcg(&g_rdown[n * EMB + d]);
                    g_zq[n * EMB + d] = zf + (q - zf);  // STE rounding
                }
            }
            __syncthreads();
            // updown own plane
            int b = blk / 24, d = blk % 24;
            if (tid < h * h) s_a[tid / h][tid % h] = g_zq[(b * h * h + tid) * EMB + d];
            __syncthreads();
            float up;
            if (h == 16) {
                up = s_a[tid >> 4][tid & 15];
            } else {
                if (tid < 16 * h) {
                    int Y = tid / h, x = tid % h;
                    float acc = 0.0f;
                    for (int y = 0; y < h; y++) acc += g_wu[s][y][Y] * s_a[y][x];
                    s_b[Y][x] = acc;
                }
                __syncthreads();
                int Y = tid >> 4, X = tid & 15;
                float acc = 0.0f;
                for (int x = 0; x < h; x++) acc += g_wu[s][x][X] * s_b[Y][x];
                up = acc;
            }
            int g = blk * 256 + tid;
            out[g] += up;
            float nr = g_res[g] - up;
            g_res[g] = nr;

            if (s < 9) {
                int hn = c_hs[s + 1];
                s_c[tid >> 4][tid & 15] = nr;
                __syncthreads();
                if (hn == 16) {  // jax resize skips equal dims -> identity
                    g_rdown[(b * 256 + tid) * EMB + d] = nr;
                } else {
                    if (tid < hn * 16) {
                        int y = tid / 16, X = tid % 16;
                        float acc = 0.0f;
                        for (int Y = 0; Y < 16; Y++)
                            acc += g_wd[s + 1][Y][y] * s_c[Y][X];
                        s_b[y][X] = acc;
                    }
                    __syncthreads();
                    if (tid < hn * hn) {
                        int y = tid / hn, x = tid % hn;
                        float acc = 0.0f;
                        for (int X = 0; X < 16; X++)
                            acc += g_wd[s + 1][X][x] * s_b[y][X];
                        g_rdown[(b * hn * hn + tid) * EMB + d] = acc;
                    }
                }
            }
        } else if (blk == 48 && s < 9) {
            unsigned long long* nxt = g_bestbuf[(s + 1) & 1];
            for (int n = tid; n < 512; n += 256) nxt[n] = 0ull;
        }
        grid_barrier(gen);
        off += N;
    }
}

// ---------------- launch ---------------------------------------------------
extern "C" void kernel_launch(void* const* d_in, const int* in_sizes, int n_in,
                              void* d_out, int out_size) {
    const float* z;
    const float* cb;
    if (in_sizes[0] == 12288) {
        z = (const float*)d_in[0];
        cb = (const float*)d_in[1];
    } else {
        z = (const float*)d_in[1];
        cb = (const float*)d_in[0];
    }
    float* out = (float*)d_out;

    int dev = 0, nsm = 148;
    cudaGetDevice(&dev);
    cudaDeviceGetAttribute(&nsm, cudaDevAttrMultiProcessorCount, dev);

    fused_kernel<<<nsm * 3, 256>>>(z, cb, out);
}

// round 16
// speedup vs baseline: 1.1664x; 1.1664x over previous
#include <cuda_runtime.h>
#include <math.h>

#define K_CB 196560
#define EMB 24
#define TT 8
#define NBARS_TOTAL 22

// ---------------- device scratch (static allocation only) ----------------
__device__ float g_res[12288];                   // residual [2][24][16][16]
__device__ float g_rdown[512 * EMB];             // downsampled tokens [N][24]
__device__ float g_zq[512 * EMB];                // quantized tokens (post-STE)
__device__ unsigned long long g_bestbuf[2][512]; // double-buffered (sim,~idx)
__device__ float g_wd[10][16][16];               // down weights
__device__ float g_wu[10][16][16];               // up weights
__device__ int g_barcnt;                         // grid barrier arrivals
__device__ int g_bargen;                         // grid barrier generation
// vector-planar codebook: plane k holds 16B-chunk k of every row,
// so a warp reading consecutive rows is fully coalesced (4 wf/LDG).
__device__ ulonglong2 g_cbT[6 * K_CB];           // 18.87 MB

__constant__ int c_hs[10] = {1, 2, 3, 4, 5, 6, 8, 10, 13, 16};

// ---------------- helpers ----------------
__device__ __forceinline__ unsigned int forder(float f) {
    unsigned int u = __float_as_uint(f);
    return (u & 0x80000000u) ? ~u : (u | 0x80000000u);
}
__device__ __forceinline__ unsigned long long ffma2(unsigned long long a,
                                                    unsigned long long b,
                                                    unsigned long long c) {
    unsigned long long d;
    asm("fma.rn.f32x2 %0, %1, %2, %3;" : "=l"(d) : "l"(a), "l"(b), "l"(c));
    return d;
}
__device__ __forceinline__ float2 unpackf2(unsigned long long v) {
    float lo, hi;
    asm("mov.b64 {%0, %1}, %2;" : "=f"(lo), "=f"(hi) : "l"(v));
    return make_float2(lo, hi);
}

// jax.image.resize compute_weight_mat (triangle kernel, antialias, tr=0)
__device__ void compute_col(int in_size, int out_size, int o, float* wcol) {
    float inv_scale = (float)((double)in_size / (double)out_size);
    float kscale = fmaxf(inv_scale, 1.0f);
    float sample_f = ((float)o + 0.5f) * inv_scale - 0.5f;
    float total = 0.0f;
    for (int i = 0; i < in_size; ++i) {
        float x = fabsf(sample_f - (float)i) / kscale;
        float w = fmaxf(0.0f, 1.0f - x);
        wcol[i] = w;
        total += w;
    }
    bool ok = fabsf(total) > 1000.0f * 1.1920928955078125e-7f;
    float denom = (total != 0.0f) ? total : 1.0f;
    bool inr = (sample_f >= -0.5f) && (sample_f <= (float)in_size - 0.5f);
    for (int i = 0; i < in_size; ++i) {
        float w = ok ? (wcol[i] / denom) : 0.0f;
        wcol[i] = inr ? w : 0.0f;
    }
}

// generation-counter grid barrier; gen is a per-thread local tracker
__device__ __forceinline__ void grid_barrier(int& gen) {
    __syncthreads();
    if (threadIdx.x == 0) {
        __threadfence();
        if (atomicAdd(&g_barcnt, 1) == (int)gridDim.x - 1) {
            atomicExch(&g_barcnt, 0);
            __threadfence();
            atomicAdd(&g_bargen, 1);
        } else {
            while (atomicAdd(&g_bargen, 0) < gen + 1) __nanosleep(64);
        }
        __threadfence();
    }
    gen++;
    __syncthreads();
}

// exact per-(row,token) dot order used since R5 (do not reorder)
#define ROW_DOT6(acc, q0, q1, q2, q3, q4, q5)                \
    do {                                                     \
        acc = ffma2(q0.x, z0.x, 0ull);                       \
        acc = ffma2(q0.y, z0.y, acc);                        \
        acc = ffma2(q1.x, z1.x, acc);                        \
        acc = ffma2(q1.y, z1.y, acc);                        \
        acc = ffma2(q2.x, z2.x, acc);                        \
        acc = ffma2(q2.y, z2.y, acc);                        \
        acc = ffma2(q3.x, z3.x, acc);                        \
        acc = ffma2(q3.y, z3.y, acc);                        \
        acc = ffma2(q4.x, z4.x, acc);                        \
        acc = ffma2(q4.y, z4.y, acc);                        \
        acc = ffma2(q5.x, z5.x, acc);                        \
        acc = ffma2(q5.y, z5.y, acc);                        \
    } while (0)

// ---------------- the whole algorithm in one persistent kernel -----------
__global__ void __launch_bounds__(256, 2)
fused_kernel(const float* __restrict__ z, const float* __restrict__ cb,
             float* __restrict__ out) {
    __shared__ __align__(16) float s_tok[TT][24];
    __shared__ unsigned long long s_wred[8][TT];
    __shared__ float s_a[16][16];
    __shared__ float s_b[16][16];
    __shared__ float s_c[16][16];
    __shared__ int s_base;

    int tid = threadIdx.x;
    int blk = blockIdx.x;
    int NB = gridDim.x;

    // per-run barrier base (replay-safe: g_bargen advances exactly
    // NBARS_TOTAL per run; all entry reads happen before first release)
    if (tid == 0) {
        int g = atomicAdd(&g_bargen, 0);
        s_base = (g / NBARS_TOTAL) * NBARS_TOTAL;
    }
    __syncthreads();
    int gen = s_base;

    // ---- phase 0: transpose codebook + residual copy + weights ----------
    {
        // coalesced read, planar scatter write (one pass, ~19MB)
        const ulonglong2* cbu = (const ulonglong2*)cb;
        for (int i = blk * 256 + tid; i < K_CB * 6; i += NB * 256) {
            int r = i / 6, k = i % 6;
            g_cbT[k * K_CB + r] = __ldg(cbu + i);
        }
    }
    if (blk < 48) {
        g_res[blk * 256 + tid] = z[blk * 256 + tid];
        out[blk * 256 + tid] = 0.0f;
        if (blk == 0) {
            for (int i = tid; i < 1024; i += 256)
                ((unsigned long long*)g_bestbuf)[i] = 0ull;
        }
    } else if (blk < 48 + 196) {
        if (tid == 0) {
            const int hs9[9] = {1, 2, 3, 4, 5, 6, 8, 10, 13};
            int task = blk - 48;
            float wcol[16];
            if (task < 52) {
                int rem = task, s = 0;
                while (rem >= hs9[s]) { rem -= hs9[s]; s++; }
                compute_col(16, hs9[s], rem, wcol);
                for (int i = 0; i < 16; i++) g_wd[s][i][rem] = wcol[i];
            } else {
                int r = task - 52;
                int s = r / 16, o = r % 16;
                compute_col(hs9[s], 16, o, wcol);
                for (int i = 0; i < 16; i++)
                    g_wu[s][i][o] = (i < hs9[s]) ? wcol[i] : 0.0f;
            }
        }
    }
    grid_barrier(gen);

    // ---- scale-0 downsample (h=1), blocks 0..47, one (b,d) plane each ---
    if (blk < 48) {
        int b = blk / 24, d = blk % 24;
        s_a[tid >> 4][tid & 15] = g_res[blk * 256 + tid];
        __syncthreads();
        if (tid < 16) {
            float acc = 0.0f;
            for (int Y = 0; Y < 16; Y++) acc += g_wd[0][Y][0] * s_a[Y][tid];
            s_b[0][tid] = acc;
        }
        __syncthreads();
        if (tid == 0) {
            float acc = 0.0f;
            for (int X = 0; X < 16; X++) acc += g_wd[0][X][0] * s_b[0][X];
            g_rdown[b * EMB + d] = acc;
        }
    }
    grid_barrier(gen);

    // ---- 10 scales ----
    int off = 12288;
    for (int s = 0; s < 10; s++) {
        int h = c_hs[s];
        int N = 2 * h * h;
        int tiles = (N + TT - 1) / TT;
        int nsl = NB / tiles;
        int tile = blk % tiles;
        int slice = blk / tiles;
        unsigned long long* best = g_bestbuf[s & 1];

        // ========= scan: R=3 rows in regs (planar), TT=8 tokens ==========
        if (slice < nsl) {
            int token0 = tile * TT;
            for (int i = tid; i < TT * 24; i += 256) {
                int t = i / 24, d = i % 24;
                int tk = token0 + t;
                s_tok[t][d] = (tk < N) ? __ldcg(&g_rdown[tk * EMB + d]) : 0.0f;
            }
            __syncthreads();

            float bestv[TT];
            int besti[TT];
#pragma unroll
            for (int t = 0; t < TT; t++) { bestv[t] = -3.4e38f; besti[t] = 0; }

            int rpb = (K_CB + nsl - 1) / nsl;
            int rbeg = slice * rpb;
            int rend = min(K_CB, rbeg + rpb);

            int base = rbeg;
            // ---- R=3 row-blocked main loop (planar coalesced loads) ----
            for (; base + 768 <= rend; base += 768) {
                int rA = base + tid, rB = rA + 256, rC = rA + 512;
                ulonglong2 a0 = __ldg(&g_cbT[0 * K_CB + rA]);
                ulonglong2 a1 = __ldg(&g_cbT[1 * K_CB + rA]);
                ulonglong2 a2 = __ldg(&g_cbT[2 * K_CB + rA]);
                ulonglong2 a3 = __ldg(&g_cbT[3 * K_CB + rA]);
                ulonglong2 a4 = __ldg(&g_cbT[4 * K_CB + rA]);
                ulonglong2 a5 = __ldg(&g_cbT[5 * K_CB + rA]);
                ulonglong2 b0 = __ldg(&g_cbT[0 * K_CB + rB]);
                ulonglong2 b1 = __ldg(&g_cbT[1 * K_CB + rB]);
                ulonglong2 b2 = __ldg(&g_cbT[2 * K_CB + rB]);
                ulonglong2 b3 = __ldg(&g_cbT[3 * K_CB + rB]);
                ulonglong2 b4 = __ldg(&g_cbT[4 * K_CB + rB]);
                ulonglong2 b5 = __ldg(&g_cbT[5 * K_CB + rB]);
                ulonglong2 c0 = __ldg(&g_cbT[0 * K_CB + rC]);
                ulonglong2 c1 = __ldg(&g_cbT[1 * K_CB + rC]);
                ulonglong2 c2 = __ldg(&g_cbT[2 * K_CB + rC]);
                ulonglong2 c3 = __ldg(&g_cbT[3 * K_CB + rC]);
                ulonglong2 c4 = __ldg(&g_cbT[4 * K_CB + rC]);
                ulonglong2 c5 = __ldg(&g_cbT[5 * K_CB + rC]);
#pragma unroll
                for (int t = 0; t < TT; t++) {
                    const ulonglong2* tz = (const ulonglong2*)s_tok[t];
                    ulonglong2 z0 = tz[0], z1 = tz[1], z2 = tz[2];
                    ulonglong2 z3 = tz[3], z4 = tz[4], z5 = tz[5];
                    unsigned long long accA, accB, accC;
                    ROW_DOT6(accA, a0, a1, a2, a3, a4, a5);
                    ROW_DOT6(accB, b0, b1, b2, b3, b4, b5);
                    ROW_DOT6(accC, c0, c1, c2, c3, c4, c5);
                    float2 fa = unpackf2(accA);
                    float2 fb = unpackf2(accB);
                    float2 fc = unpackf2(accC);
                    float simA = fa.x + fa.y;
                    float simB = fb.x + fb.y;
                    float simC = fc.x + fc.y;
                    if (simA > bestv[t]) { bestv[t] = simA; besti[t] = rA; }
                    if (simB > bestv[t]) { bestv[t] = simB; besti[t] = rB; }
                    if (simC > bestv[t]) { bestv[t] = simC; besti[t] = rC; }
                }
            }
            // ---- tail: single rows ----
            for (int r = base + tid; r < rend; r += 256) {
                ulonglong2 q0 = __ldg(&g_cbT[0 * K_CB + r]);
                ulonglong2 q1 = __ldg(&g_cbT[1 * K_CB + r]);
                ulonglong2 q2 = __ldg(&g_cbT[2 * K_CB + r]);
                ulonglong2 q3 = __ldg(&g_cbT[3 * K_CB + r]);
                ulonglong2 q4 = __ldg(&g_cbT[4 * K_CB + r]);
                ulonglong2 q5 = __ldg(&g_cbT[5 * K_CB + r]);
#pragma unroll
                for (int t = 0; t < TT; t++) {
                    const ulonglong2* tz = (const ulonglong2*)s_tok[t];
                    ulonglong2 z0 = tz[0], z1 = tz[1], z2 = tz[2];
                    ulonglong2 z3 = tz[3], z4 = tz[4], z5 = tz[5];
                    unsigned long long acc;
                    ROW_DOT6(acc, q0, q1, q2, q3, q4, q5);
                    float2 s2 = unpackf2(acc);
                    float sim = s2.x + s2.y;
                    if (sim > bestv[t]) { bestv[t] = sim; besti[t] = r; }
                }
            }

            unsigned long long pk[TT];
#pragma unroll
            for (int t = 0; t < TT; t++)
                pk[t] = ((unsigned long long)forder(bestv[t]) << 32) |
                        (unsigned long long)((unsigned)~besti[t]);
#pragma unroll
            for (int t = 0; t < TT; t++) {
#pragma unroll
                for (int o2 = 16; o2; o2 >>= 1) {
                    unsigned long long o = __shfl_down_sync(0xFFFFFFFFu, pk[t], o2);
                    if (o > pk[t]) pk[t] = o;
                }
            }
            int warp = tid >> 5, lane = tid & 31;
            if (lane == 0) {
#pragma unroll
                for (int t = 0; t < TT; t++) s_wred[warp][t] = pk[t];
            }
            __syncthreads();
            if (tid < TT) {
                unsigned long long m = s_wred[0][tid];
#pragma unroll
                for (int w = 1; w < 8; w++) {
                    unsigned long long v = s_wred[w][tid];
                    if (v > m) m = v;
                }
                if (token0 + tid < N) atomicMax(&best[token0 + tid], m);
            }
        }
        grid_barrier(gen);

        // ============ finalize (redundant per block) + updown ============
        if (blk < 48) {
            // finalize all N tokens (identical values from every block)
            for (int n = tid; n < N; n += 256) {
                unsigned long long pkv = __ldcg(&best[n]);
                unsigned row = ~((unsigned)(pkv & 0xFFFFFFFFull));
                out[off + n] = (float)row;
                const float* c = cb + (size_t)row * EMB;
                float ss = 0.0f;
                for (int d = 0; d < EMB; d++) { float v = c[d]; ss += v * v; }
                float nrm = sqrtf(ss);
                for (int d = 0; d < EMB; d++) {
                    float q = c[d] / nrm;
                    float zf = __ldcg(&g_rdown[n * EMB + d]);
                    g_zq[n * EMB + d] = zf + (q - zf);  // STE rounding
                }
            }
            __syncthreads();
            // updown own plane
            int b = blk / 24, d = blk % 24;
            if (tid < h * h) s_a[tid / h][tid % h] = g_zq[(b * h * h + tid) * EMB + d];
            __syncthreads();
            float up;
            if (h == 16) {
                up = s_a[tid >> 4][tid & 15];
            } else {
                if (tid < 16 * h) {
                    int Y = tid / h, x = tid % h;
                    float acc = 0.0f;
                    for (int y = 0; y < h; y++) acc += g_wu[s][y][Y] * s_a[y][x];
                    s_b[Y][x] = acc;
                }
                __syncthreads();
                int Y = tid >> 4, X = tid & 15;
                float acc = 0.0f;
                for (int x = 0; x < h; x++) acc += g_wu[s][x][X] * s_b[Y][x];
                up = acc;
            }
            int g = blk * 256 + tid;
            out[g] += up;
            float nr = g_res[g] - up;
            g_res[g] = nr;

            if (s < 9) {
                int hn = c_hs[s + 1];
                s_c[tid >> 4][tid & 15] = nr;
                __syncthreads();
                if (hn == 16) {  // jax resize skips equal dims -> identity
                    g_rdown[(b * 256 + tid) * EMB + d] = nr;
                } else {
                    if (tid < hn * 16) {
                        int y = tid / 16, X = tid % 16;
                        float acc = 0.0f;
                        for (int Y = 0; Y < 16; Y++)
                            acc += g_wd[s + 1][Y][y] * s_c[Y][X];
                        s_b[y][X] = acc;
                    }
                    __syncthreads();
                    if (tid < hn * hn) {
                        int y = tid / hn, x = tid % hn;
                        float acc = 0.0f;
                        for (int X = 0; X < 16; X++)
                            acc += g_wd[s + 1][X][x] * s_b[y][X];
                        g_rdown[(b * hn * hn + tid) * EMB + d] = acc;
                    }
                }
            }
        } else if (blk == 48 && s < 9) {
            unsigned long long* nxt = g_bestbuf[(s + 1) & 1];
            for (int n = tid; n < 512; n += 256) nxt[n] = 0ull;
        }
        grid_barrier(gen);
        off += N;
    }
}

// ---------------- launch ---------------------------------------------------
extern "C" void kernel_launch(void* const* d_in, const int* in_sizes, int n_in,
                              void* d_out, int out_size) {
    const float* z;
    const float* cb;
    if (in_sizes[0] == 12288) {
        z = (const float*)d_in[0];
        cb = (const float*)d_in[1];
    } else {
        z = (const float*)d_in[1];
        cb = (const float*)d_in[0];
    }
    float* out = (float*)d_out;

    int dev = 0, nsm = 148;
    cudaGetDevice(&dev);
    cudaDeviceGetAttribute(&nsm, cudaDevAttrMultiProcessorCount, dev);

    fused_kernel<<<nsm * 2, 256>>>(z, cb, out);
}

// round 17
// speedup vs baseline: 1.1769x; 1.0090x over previous
#include <cuda_runtime.h>
#include <math.h>

#define K_CB 196560
#define EMB 24
#define TT 8
#define NBARS_TOTAL 22

// ---------------- device scratch (static allocation only) ----------------
__device__ float g_res[12288];                   // residual [2][24][16][16]
__device__ float g_rdown[512 * EMB];             // downsampled tokens [N][24]
__device__ float g_zq[512 * EMB];                // quantized tokens (post-STE)
__device__ unsigned long long g_bestbuf[2][512]; // double-buffered (sim,~idx)
__device__ float g_wd[10][16][16];               // down weights
__device__ float g_wu[10][16][16];               // up weights
__device__ int g_barcnt;                         // grid barrier arrivals
__device__ int g_bargen;                         // grid barrier generation
// vector-planar codebook: plane k holds 16B-chunk k of every row,
// so a warp reading consecutive rows is fully coalesced (4 wf/LDG).
__device__ ulonglong2 g_cbT[6 * K_CB];           // 18.87 MB

__constant__ int c_hs[10] = {1, 2, 3, 4, 5, 6, 8, 10, 13, 16};

// ---------------- helpers ----------------
__device__ __forceinline__ unsigned int forder(float f) {
    unsigned int u = __float_as_uint(f);
    return (u & 0x80000000u) ? ~u : (u | 0x80000000u);
}
__device__ __forceinline__ unsigned long long ffma2(unsigned long long a,
                                                    unsigned long long b,
                                                    unsigned long long c) {
    unsigned long long d;
    asm("fma.rn.f32x2 %0, %1, %2, %3;" : "=l"(d) : "l"(a), "l"(b), "l"(c));
    return d;
}
__device__ __forceinline__ float2 unpackf2(unsigned long long v) {
    float lo, hi;
    asm("mov.b64 {%0, %1}, %2;" : "=f"(lo), "=f"(hi) : "l"(v));
    return make_float2(lo, hi);
}

// jax.image.resize compute_weight_mat (triangle kernel, antialias, tr=0)
__device__ void compute_col(int in_size, int out_size, int o, float* wcol) {
    float inv_scale = (float)((double)in_size / (double)out_size);
    float kscale = fmaxf(inv_scale, 1.0f);
    float sample_f = ((float)o + 0.5f) * inv_scale - 0.5f;
    float total = 0.0f;
    for (int i = 0; i < in_size; ++i) {
        float x = fabsf(sample_f - (float)i) / kscale;
        float w = fmaxf(0.0f, 1.0f - x);
        wcol[i] = w;
        total += w;
    }
    bool ok = fabsf(total) > 1000.0f * 1.1920928955078125e-7f;
    float denom = (total != 0.0f) ? total : 1.0f;
    bool inr = (sample_f >= -0.5f) && (sample_f <= (float)in_size - 0.5f);
    for (int i = 0; i < in_size; ++i) {
        float w = ok ? (wcol[i] / denom) : 0.0f;
        wcol[i] = inr ? w : 0.0f;
    }
}

// generation-counter grid barrier; gen is a per-thread local tracker
__device__ __forceinline__ void grid_barrier(int& gen) {
    __syncthreads();
    if (threadIdx.x == 0) {
        __threadfence();
        if (atomicAdd(&g_barcnt, 1) == (int)gridDim.x - 1) {
            atomicExch(&g_barcnt, 0);
            __threadfence();
            atomicAdd(&g_bargen, 1);
        } else {
            while (atomicAdd(&g_bargen, 0) < gen + 1) __nanosleep(32);
        }
        __threadfence();
    }
    gen++;
    __syncthreads();
}

// Three interleaved row-dot chains. Each accumulator's own FMA order is
// IDENTICAL to ROW_DOT6 (bit-exact); interleaving only adds explicit ILP.
#define ROW_DOT3I(accA, accB, accC)                          \
    do {                                                     \
        accA = ffma2(a0.x, z0.x, 0ull);                      \
        accB = ffma2(b0.x, z0.x, 0ull);                      \
        accC = ffma2(c0.x, z0.x, 0ull);                      \
        accA = ffma2(a0.y, z0.y, accA);                      \
        accB = ffma2(b0.y, z0.y, accB);                      \
        accC = ffma2(c0.y, z0.y, accC);                      \
        accA = ffma2(a1.x, z1.x, accA);                      \
        accB = ffma2(b1.x, z1.x, accB);                      \
        accC = ffma2(c1.x, z1.x, accC);                      \
        accA = ffma2(a1.y, z1.y, accA);                      \
        accB = ffma2(b1.y, z1.y, accB);                      \
        accC = ffma2(c1.y, z1.y, accC);                      \
        accA = ffma2(a2.x, z2.x, accA);                      \
        accB = ffma2(b2.x, z2.x, accB);                      \
        accC = ffma2(c2.x, z2.x, accC);                      \
        accA = ffma2(a2.y, z2.y, accA);                      \
        accB = ffma2(b2.y, z2.y, accB);                      \
        accC = ffma2(c2.y, z2.y, accC);                      \
        accA = ffma2(a3.x, z3.x, accA);                      \
        accB = ffma2(b3.x, z3.x, accB);                      \
        accC = ffma2(c3.x, z3.x, accC);                      \
        accA = ffma2(a3.y, z3.y, accA);                      \
        accB = ffma2(b3.y, z3.y, accB);                      \
        accC = ffma2(c3.y, z3.y, accC);                      \
        accA = ffma2(a4.x, z4.x, accA);                      \
        accB = ffma2(b4.x, z4.x, accB);                      \
        accC = ffma2(c4.x, z4.x, accC);                      \
        accA = ffma2(a4.y, z4.y, accA);                      \
        accB = ffma2(b4.y, z4.y, accB);                      \
        accC = ffma2(c4.y, z4.y, accC);                      \
        accA = ffma2(a5.x, z5.x, accA);                      \
        accB = ffma2(b5.x, z5.x, accB);                      \
        accC = ffma2(c5.x, z5.x, accC);                      \
        accA = ffma2(a5.y, z5.y, accA);                      \
        accB = ffma2(b5.y, z5.y, accB);                      \
        accC = ffma2(c5.y, z5.y, accC);                      \
    } while (0)

// single-row dot (tail), exact order as before
#define ROW_DOT6(acc, q0, q1, q2, q3, q4, q5)                \
    do {                                                     \
        acc = ffma2(q0.x, z0.x, 0ull);                       \
        acc = ffma2(q0.y, z0.y, acc);                        \
        acc = ffma2(q1.x, z1.x, acc);                        \
        acc = ffma2(q1.y, z1.y, acc);                        \
        acc = ffma2(q2.x, z2.x, acc);                        \
        acc = ffma2(q2.y, z2.y, acc);                        \
        acc = ffma2(q3.x, z3.x, acc);                        \
        acc = ffma2(q3.y, z3.y, acc);                        \
        acc = ffma2(q4.x, z4.x, acc);                        \
        acc = ffma2(q4.y, z4.y, acc);                        \
        acc = ffma2(q5.x, z5.x, acc);                        \
        acc = ffma2(q5.y, z5.y, acc);                        \
    } while (0)

// ---------------- the whole algorithm in one persistent kernel -----------
__global__ void __launch_bounds__(256, 2)
fused_kernel(const float* __restrict__ z, const float* __restrict__ cb,
             float* __restrict__ out) {
    __shared__ __align__(16) float s_tok[TT][24];
    __shared__ unsigned long long s_wred[8][TT];
    __shared__ float s_a[16][16];
    __shared__ float s_b[16][16];
    __shared__ float s_c[16][16];
    __shared__ int s_base;

    int tid = threadIdx.x;
    int blk = blockIdx.x;
    int NB = gridDim.x;

    // per-run barrier base (replay-safe: g_bargen advances exactly
    // NBARS_TOTAL per run; all entry reads happen before first release)
    if (tid == 0) {
        int g = atomicAdd(&g_bargen, 0);
        s_base = (g / NBARS_TOTAL) * NBARS_TOTAL;
    }
    __syncthreads();
    int gen = s_base;

    // ---- phase 0: transpose codebook + residual copy + weights ----------
    {
        // coalesced read, planar scatter write (one pass, ~19MB)
        const ulonglong2* cbu = (const ulonglong2*)cb;
        for (int i = blk * 256 + tid; i < K_CB * 6; i += NB * 256) {
            int r = i / 6, k = i % 6;
            g_cbT[k * K_CB + r] = __ldg(cbu + i);
        }
    }
    if (blk < 48) {
        g_res[blk * 256 + tid] = z[blk * 256 + tid];
        out[blk * 256 + tid] = 0.0f;
        if (blk == 0) {
            for (int i = tid; i < 1024; i += 256)
                ((unsigned long long*)g_bestbuf)[i] = 0ull;
        }
    } else if (blk < 48 + 196) {
        if (tid == 0) {
            const int hs9[9] = {1, 2, 3, 4, 5, 6, 8, 10, 13};
            int task = blk - 48;
            float wcol[16];
            if (task < 52) {
                int rem = task, s = 0;
                while (rem >= hs9[s]) { rem -= hs9[s]; s++; }
                compute_col(16, hs9[s], rem, wcol);
                for (int i = 0; i < 16; i++) g_wd[s][i][rem] = wcol[i];
            } else {
                int r = task - 52;
                int s = r / 16, o = r % 16;
                compute_col(hs9[s], 16, o, wcol);
                for (int i = 0; i < 16; i++)
                    g_wu[s][i][o] = (i < hs9[s]) ? wcol[i] : 0.0f;
            }
        }
    }
    grid_barrier(gen);

    // ---- scale-0 downsample (h=1), blocks 0..47, one (b,d) plane each ---
    if (blk < 48) {
        int b = blk / 24, d = blk % 24;
        s_a[tid >> 4][tid & 15] = g_res[blk * 256 + tid];
        __syncthreads();
        if (tid < 16) {
            float acc = 0.0f;
            for (int Y = 0; Y < 16; Y++) acc += g_wd[0][Y][0] * s_a[Y][tid];
            s_b[0][tid] = acc;
        }
        __syncthreads();
        if (tid == 0) {
            float acc = 0.0f;
            for (int X = 0; X < 16; X++) acc += g_wd[0][X][0] * s_b[0][X];
            g_rdown[b * EMB + d] = acc;
        }
    }
    grid_barrier(gen);

    // ---- 10 scales ----
    int off = 12288;
    for (int s = 0; s < 10; s++) {
        int h = c_hs[s];
        int N = 2 * h * h;
        int tiles = (N + TT - 1) / TT;
        int nsl = NB / tiles;
        int tile = blk % tiles;
        int slice = blk / tiles;
        unsigned long long* best = g_bestbuf[s & 1];

        // ========= scan: R=3 rows in regs (planar), TT=8 tokens ==========
        if (slice < nsl) {
            int token0 = tile * TT;
            for (int i = tid; i < TT * 24; i += 256) {
                int t = i / 24, d = i % 24;
                int tk = token0 + t;
                s_tok[t][d] = (tk < N) ? __ldcg(&g_rdown[tk * EMB + d]) : 0.0f;
            }
            __syncthreads();

            float bestv[TT];
            int besti[TT];
#pragma unroll
            for (int t = 0; t < TT; t++) { bestv[t] = -3.4e38f; besti[t] = 0; }

            int rpb = (K_CB + nsl - 1) / nsl;
            int rbeg = slice * rpb;
            int rend = min(K_CB, rbeg + rpb);

            int base = rbeg;
            // ---- R=3 row-blocked main loop (planar coalesced loads) ----
            for (; base + 768 <= rend; base += 768) {
                int rA = base + tid, rB = rA + 256, rC = rA + 512;
                ulonglong2 a0 = __ldg(&g_cbT[0 * K_CB + rA]);
                ulonglong2 a1 = __ldg(&g_cbT[1 * K_CB + rA]);
                ulonglong2 a2 = __ldg(&g_cbT[2 * K_CB + rA]);
                ulonglong2 a3 = __ldg(&g_cbT[3 * K_CB + rA]);
                ulonglong2 a4 = __ldg(&g_cbT[4 * K_CB + rA]);
                ulonglong2 a5 = __ldg(&g_cbT[5 * K_CB + rA]);
                ulonglong2 b0 = __ldg(&g_cbT[0 * K_CB + rB]);
                ulonglong2 b1 = __ldg(&g_cbT[1 * K_CB + rB]);
                ulonglong2 b2 = __ldg(&g_cbT[2 * K_CB + rB]);
                ulonglong2 b3 = __ldg(&g_cbT[3 * K_CB + rB]);
                ulonglong2 b4 = __ldg(&g_cbT[4 * K_CB + rB]);
                ulonglong2 b5 = __ldg(&g_cbT[5 * K_CB + rB]);
                ulonglong2 c0 = __ldg(&g_cbT[0 * K_CB + rC]);
                ulonglong2 c1 = __ldg(&g_cbT[1 * K_CB + rC]);
                ulonglong2 c2 = __ldg(&g_cbT[2 * K_CB + rC]);
                ulonglong2 c3 = __ldg(&g_cbT[3 * K_CB + rC]);
                ulonglong2 c4 = __ldg(&g_cbT[4 * K_CB + rC]);
                ulonglong2 c5 = __ldg(&g_cbT[5 * K_CB + rC]);
#pragma unroll
                for (int t = 0; t < TT; t++) {
                    const ulonglong2* tz = (const ulonglong2*)s_tok[t];
                    ulonglong2 z0 = tz[0], z1 = tz[1], z2 = tz[2];
                    ulonglong2 z3 = tz[3], z4 = tz[4], z5 = tz[5];
                    unsigned long long accA, accB, accC;
                    ROW_DOT3I(accA, accB, accC);
                    float2 fa = unpackf2(accA);
                    float2 fb = unpackf2(accB);
                    float2 fc = unpackf2(accC);
                    float simA = fa.x + fa.y;
                    float simB = fb.x + fb.y;
                    float simC = fc.x + fc.y;
                    // group max; first-max-wins == sequential A->B->C strict >
                    float m = fmaxf(fmaxf(simA, simB), simC);
                    if (m > bestv[t]) {
                        bestv[t] = m;
                        besti[t] = (simA == m) ? rA : ((simB == m) ? rB : rC);
                    }
                }
            }
            // ---- tail: single rows ----
            for (int r = base + tid; r < rend; r += 256) {
                ulonglong2 q0 = __ldg(&g_cbT[0 * K_CB + r]);
                ulonglong2 q1 = __ldg(&g_cbT[1 * K_CB + r]);
                ulonglong2 q2 = __ldg(&g_cbT[2 * K_CB + r]);
                ulonglong2 q3 = __ldg(&g_cbT[3 * K_CB + r]);
                ulonglong2 q4 = __ldg(&g_cbT[4 * K_CB + r]);
                ulonglong2 q5 = __ldg(&g_cbT[5 * K_CB + r]);
#pragma unroll
                for (int t = 0; t < TT; t++) {
                    const ulonglong2* tz = (const ulonglong2*)s_tok[t];
                    ulonglong2 z0 = tz[0], z1 = tz[1], z2 = tz[2];
                    ulonglong2 z3 = tz[3], z4 = tz[4], z5 = tz[5];
                    unsigned long long acc;
                    ROW_DOT6(acc, q0, q1, q2, q3, q4, q5);
                    float2 s2 = unpackf2(acc);
                    float sim = s2.x + s2.y;
                    if (sim > bestv[t]) { bestv[t] = sim; besti[t] = r; }
                }
            }

            unsigned long long pk[TT];
#pragma unroll
            for (int t = 0; t < TT; t++)
                pk[t] = ((unsigned long long)forder(bestv[t]) << 32) |
                        (unsigned long long)((unsigned)~besti[t]);
#pragma unroll
            for (int t = 0; t < TT; t++) {
#pragma unroll
                for (int o2 = 16; o2; o2 >>= 1) {
                    unsigned long long o = __shfl_down_sync(0xFFFFFFFFu, pk[t], o2);
                    if (o > pk[t]) pk[t] = o;
                }
            }
            int warp = tid >> 5, lane = tid & 31;
            if (lane == 0) {
#pragma unroll
                for (int t = 0; t < TT; t++) s_wred[warp][t] = pk[t];
            }
            __syncthreads();
            if (tid < TT) {
                unsigned long long m = s_wred[0][tid];
#pragma unroll
                for (int w = 1; w < 8; w++) {
                    unsigned long long v = s_wred[w][tid];
                    if (v > m) m = v;
                }
                if (token0 + tid < N) atomicMax(&best[token0 + tid], m);
            }
        }
        grid_barrier(gen);

        // ============ finalize (redundant per block) + updown ============
        if (blk < 48) {
            // finalize all N tokens (identical values from every block)
            for (int n = tid; n < N; n += 256) {
                unsigned long long pkv = __ldcg(&best[n]);
                unsigned row = ~((unsigned)(pkv & 0xFFFFFFFFull));
                out[off + n] = (float)row;
                const float* c = cb + (size_t)row * EMB;
                float ss = 0.0f;
                for (int d = 0; d < EMB; d++) { float v = c[d]; ss += v * v; }
                float nrm = sqrtf(ss);
                for (int d = 0; d < EMB; d++) {
                    float q = c[d] / nrm;
                    float zf = __ldcg(&g_rdown[n * EMB + d]);
                    g_zq[n * EMB + d] = zf + (q - zf);  // STE rounding
                }
            }
            __syncthreads();
            // updown own plane
            int b = blk / 24, d = blk % 24;
            if (tid < h * h) s_a[tid / h][tid % h] = g_zq[(b * h * h + tid) * EMB + d];
            __syncthreads();
            float up;
            if (h == 16) {
                up = s_a[tid >> 4][tid & 15];
            } else {
                if (tid < 16 * h) {
                    int Y = tid / h, x = tid % h;
                    float acc = 0.0f;
                    for (int y = 0; y < h; y++) acc += g_wu[s][y][Y] * s_a[y][x];
                    s_b[Y][x] = acc;
                }
                __syncthreads();
                int Y = tid >> 4, X = tid & 15;
                float acc = 0.0f;
                for (int x = 0; x < h; x++) acc += g_wu[s][x][X] * s_b[Y][x];
                up = acc;
            }
            int g = blk * 256 + tid;
            out[g] += up;
            float nr = g_res[g] - up;
            g_res[g] = nr;

            if (s < 9) {
                int hn = c_hs[s + 1];
                s_c[tid >> 4][tid & 15] = nr;
                __syncthreads();
                if (hn == 16) {  // jax resize skips equal dims -> identity
                    g_rdown[(b * 256 + tid) * EMB + d] = nr;
                } else {
                    if (tid < hn * 16) {
                        int y = tid / 16, X = tid % 16;
                        float acc = 0.0f;
                        for (int Y = 0; Y < 16; Y++)
                            acc += g_wd[s + 1][Y][y] * s_c[Y][X];
                        s_b[y][X] = acc;
                    }
                    __syncthreads();
                    if (tid < hn * hn) {
                        int y = tid / hn, x = tid % hn;
                        float acc = 0.0f;
                        for (int X = 0; X < 16; X++)
                            acc += g_wd[s + 1][X][x] * s_b[y][X];
                        g_rdown[(b * hn * hn + tid) * EMB + d] = acc;
                    }
                }
            }
        } else if (blk == 48 && s < 9) {
            unsigned long long* nxt = g_bestbuf[(s + 1) & 1];
            for (int n = tid; n < 512; n += 256) nxt[n] = 0ull;
        }
        grid_barrier(gen);
        off += N;
    }
}

// ---------------- launch ---------------------------------------------------
extern "C" void kernel_launch(void* const* d_in, const int* in_sizes, int n_in,
                              void* d_out, int out_size) {
    const float* z;
    const float* cb;
    if (in_sizes[0] == 12288) {
        z = (const float*)d_in[0];
        cb = (const float*)d_in[1];
    } else {
        z = (const float*)d_in[1];
        cb = (const float*)d_in[0];
    }
    float* out = (float*)d_out;

    int dev = 0, nsm = 148;
    cudaGetDevice(&dev);
    cudaDeviceGetAttribute(&nsm, cudaDevAttrMultiProcessorCount, dev);

    fused_kernel<<<nsm * 2, 256>>>(z, cb, out);
}